// round 17
// baseline (speedup 1.0000x reference)
#include <cuda_runtime.h>
#include <math.h>
#include <stdint.h>

#define DHC   512
#define NMAX  50000
#define EMAX  400000
#define GMAX  8

// ---------------- scratch (static device globals; no runtime allocation) ----
// __device__ symbols only referenced from device code (R8 aliasing bug).
__device__ float  g_h[(size_t)NMAX * DHC];      // h = x @ W
__device__ float  g_hconv[(size_t)NMAX * DHC];  // GAT output (pre-rounded bits)
__device__ float  g_xn[(size_t)NMAX * DHC];     // hconv @ Wn + bn
__device__ float  g_xr[(size_t)NMAX * DHC];     // x pre-rounded for tf32
__device__ float  g_wr[512 * 512];              // W  pre-rounded
__device__ float  g_wnr[512 * 512];             // Wn pre-rounded
__device__ float  g_as[NMAX];
__device__ float  g_ad[NMAX];
__device__ float  g_ex[EMAX + NMAX];
__device__ float  g_gex[NMAX];
__device__ float  g_g[NMAX];
__device__ float  g_gsum[GMAX];
__device__ double g_pooled[GMAX * DHC];
__device__ float  g_z1[GMAX * DHC];
__device__ int    g_src[EMAX];
__device__ int    g_dst[EMAX];
__device__ int    g_b[NMAX];
// CSR (incoming edges per node)
__device__ int    g_deg[NMAX];
__device__ int    g_off[NMAX + 1];
__device__ int    g_cur[NMAX];
__device__ int    g_cs[EMAX];
__device__ int    g_ce[EMAX];

// ---------------- helpers ----------------------------------------------------
__device__ __forceinline__ uint32_t smem_u32(const void* p) {
    uint32_t a;
    asm("{ .reg .u64 t; cvta.to.shared.u64 t, %1; cvt.u32.u64 %0, t; }"
        : "=r"(a) : "l"(p));
    return a;
}

// store bits+half-ULP(tf32): later MMA bit-truncation == round-to-nearest
__device__ __forceinline__ float pre_rnd(float f) {
    return __uint_as_float(__float_as_uint(f) + 0x1000u);
}

__device__ __forceinline__ void mma_tf32(float d[4], const uint32_t a[4],
                                         const uint32_t b[2]) {
    asm volatile(
        "mma.sync.aligned.m16n8k8.row.col.f32.tf32.tf32.f32 "
        "{%0,%1,%2,%3}, {%4,%5,%6,%7}, {%8,%9}, {%0,%1,%2,%3};"
        : "+f"(d[0]), "+f"(d[1]), "+f"(d[2]), "+f"(d[3])
        : "r"(a[0]), "r"(a[1]), "r"(a[2]), "r"(a[3]), "r"(b[0]), "r"(b[1]));
}

// ---------------- setup ------------------------------------------------------
__global__ void setup_kernel(float* out, int out_size, int Nn) {
    int stride = gridDim.x * blockDim.x;
    int lim = out_size > Nn ? out_size : Nn;
    for (int i = blockIdx.x * blockDim.x + threadIdx.x; i < lim; i += stride) {
        if (i < out_size)    out[i] = 0.0f;
        if (i < Nn)          g_deg[i] = 0;
        if (i < GMAX)        g_gsum[i] = 0.0f;
        if (i < GMAX * DHC)  g_pooled[i] = 0.0;
    }
}

__global__ void decode_kernel(const void* __restrict__ ei,
                              const void* __restrict__ bp, int E, int Nn,
                              int is64e, int is64b) {
    int i = blockIdx.x * blockDim.x + threadIdx.x;
    if (i < E) {
        if (is64e) {
            g_src[i] = (int)((const long long*)ei)[i];
            g_dst[i] = (int)((const long long*)ei)[E + i];
        } else {
            g_src[i] = ((const int*)ei)[i];
            g_dst[i] = ((const int*)ei)[E + i];
        }
    }
    if (i < Nn)
        g_b[i] = is64b ? (int)((const long long*)bp)[i] : ((const int*)bp)[i];
}

// pre-round x, W, Wn into tf32-rna-equivalent bit patterns
__global__ void pre_round_kernel(const float* __restrict__ x,
                                 const float* __restrict__ W,
                                 const float* __restrict__ Wn, int Nn) {
    long long nx = (long long)Nn * DHC;
    long long tot = nx + 2 * 262144;
    long long stride = (long long)gridDim.x * blockDim.x;
    for (long long i = (long long)blockIdx.x * blockDim.x + threadIdx.x;
         i < tot; i += stride) {
        if (i < nx)                 g_xr[i] = pre_rnd(x[i]);
        else if (i < nx + 262144)   g_wr[i - nx] = pre_rnd(W[i - nx]);
        else                        g_wnr[i - nx - 262144] = pre_rnd(Wn[i - nx - 262144]);
    }
}

// ---------------- CSR build ---------------------------------------------------
__global__ void hist_kernel(int E) {
    int i = blockIdx.x * blockDim.x + threadIdx.x;
    if (i < E) atomicAdd(&g_deg[g_dst[i]], 1);
}

__global__ __launch_bounds__(1024)
void scan_kernel(int Nn) {
    __shared__ int warp_sums[32];
    __shared__ int carry;
    if (threadIdx.x == 0) carry = 0;
    __syncthreads();
    int lane = threadIdx.x & 31, wid = threadIdx.x >> 5;
    int nchunk = (Nn + 1023) >> 10;
    for (int c = 0; c < nchunk; c++) {
        int i = (c << 10) + threadIdx.x;
        int v = (i < Nn) ? g_deg[i] : 0;
        int x = v;
#pragma unroll
        for (int o = 1; o < 32; o <<= 1) {
            int y = __shfl_up_sync(0xffffffffu, x, o);
            if (lane >= o) x += y;
        }
        if (lane == 31) warp_sums[wid] = x;
        __syncthreads();
        if (wid == 0) {
            int s = warp_sums[lane];
#pragma unroll
            for (int o = 1; o < 32; o <<= 1) {
                int y = __shfl_up_sync(0xffffffffu, s, o);
                if (lane >= o) s += y;
            }
            warp_sums[lane] = s;
        }
        __syncthreads();
        int incl = x + (wid > 0 ? warp_sums[wid - 1] : 0) + carry;
        if (i < Nn) { g_off[i] = incl - v; g_cur[i] = incl - v; }
        __syncthreads();
        if (threadIdx.x == 1023) carry = incl;
        __syncthreads();
    }
    if (threadIdx.x == 0) g_off[Nn] = carry;
}

__global__ void scatter_kernel(int E) {
    int i = blockIdx.x * blockDim.x + threadIdx.x;
    if (i >= E) return;
    int d = g_dst[i];
    int pos = atomicAdd(&g_cur[d], 1);
    g_cs[pos] = g_src[i];
    g_ce[pos] = i;
}

// ---------------- TF32 GEMM ---------------------------------------------------
// C[M,512] = A[M,512] @ B[512,512] (+bias); operands pre-rounded in memory.
// mode 0: A=g_xr,    B=g_wr,  C=g_h
// mode 1: A=g_hconv, B=g_wnr, C=g_xn
// 128x128 block tile, 4 warps (2x2), warp tile 64x64, BK=16,
// 3-stage cp.async ring with ONE barrier per iteration, dynamic SMEM.
#define BM 128
#define BN 128
#define BK 16
#define NT 32
#define AS_LD 20
#define BS_LD 132
#define AS_STG (BM * AS_LD)          // 2560 floats / stage
#define BS_STG (BK * BS_LD)          // 2112 floats / stage
#define SMEM_FLOATS (3 * (AS_STG + BS_STG))
#define SMEM_BYTES  (SMEM_FLOATS * 4)

extern __shared__ float smem_dyn[];

__global__ __launch_bounds__(128)
void sgemm_tf32_kernel(const float* __restrict__ bias, int M, int mode) {
    const float* A = (mode == 0) ? g_xr : g_hconv;
    const float* B = (mode == 0) ? g_wr : g_wnr;
    float*       C = (mode == 0) ? g_h  : g_xn;

    float* Abuf = smem_dyn;                     // [3][BM][AS_LD]
    float* Bbuf = smem_dyn + 3 * AS_STG;        // [3][BK][BS_LD]

    const int bm = blockIdx.y * BM;
    const int bn = blockIdx.x * BN;
    const int tid  = threadIdx.x;
    const int lane = tid & 31, warp = tid >> 5;
    const int wm = warp & 1;            // 2 m-slabs of 64
    const int wn = warp >> 1;           // 2 n-slabs of 64
    const int gid = lane >> 2;          // 0..7
    const int tig = lane & 3;           // 0..3

    float d[4][8][4];
#pragma unroll
    for (int mt = 0; mt < 4; mt++)
#pragma unroll
        for (int nt = 0; nt < 8; nt++)
#pragma unroll
            for (int r = 0; r < 4; r++) d[mt][nt][r] = 0.0f;

    auto load_tiles = [&](int st, int k0) {
        float* As = Abuf + st * AS_STG;
        float* Bs = Bbuf + st * BS_STG;
#pragma unroll
        for (int t = 0; t < 4; t++) {           // A: 512 chunks of 16B
            int ch = tid + t * 128;
            int r = ch >> 2, k4 = ch & 3;
            int grow = bm + r;
            int srow = grow < M ? grow : (M - 1);
            uint32_t dst = smem_u32(&As[r * AS_LD + k4 * 4]);
            const float* src = &A[(size_t)srow * 512 + k0 + k4 * 4];
            int sz = (grow < M) ? 16 : 0;
            asm volatile("cp.async.ca.shared.global [%0], [%1], 16, %2;"
                         :: "r"(dst), "l"(src), "r"(sz));
        }
#pragma unroll
        for (int t = 0; t < 4; t++) {           // B: 512 chunks of 16B
            int ch = tid + t * 128;
            int r = ch >> 5, c = ch & 31;
            uint32_t dst = smem_u32(&Bs[r * BS_LD + c * 4]);
            const float* src = &B[(size_t)(k0 + r) * 512 + bn + c * 4];
            asm volatile("cp.async.ca.shared.global [%0], [%1], 16;"
                         :: "r"(dst), "l"(src));
        }
    };

    load_tiles(0, 0);
    asm volatile("cp.async.commit_group;");
    load_tiles(1, BK);
    asm volatile("cp.async.commit_group;");

    for (int t = 0; t < NT; t++) {
        if (t + 2 < NT) asm volatile("cp.async.wait_group 1;");
        else            asm volatile("cp.async.wait_group 0;");
        __syncthreads();
        if (t + 2 < NT) {
            load_tiles((t + 2) % 3, (t + 2) * BK);
            asm volatile("cp.async.commit_group;");
        }
        const float* As = Abuf + (t % 3) * AS_STG;
        const float* Bs = Bbuf + (t % 3) * BS_STG;
#pragma unroll
        for (int kc = 0; kc < BK; kc += 8) {
            uint32_t a[4][4], b[8][2];
#pragma unroll
            for (int mt = 0; mt < 4; mt++) {
                int mrow = wm * 64 + mt * 16 + gid;
                a[mt][0] = __float_as_uint(As[mrow * AS_LD + kc + tig]);
                a[mt][1] = __float_as_uint(As[(mrow + 8) * AS_LD + kc + tig]);
                a[mt][2] = __float_as_uint(As[mrow * AS_LD + kc + tig + 4]);
                a[mt][3] = __float_as_uint(As[(mrow + 8) * AS_LD + kc + tig + 4]);
            }
#pragma unroll
            for (int nt = 0; nt < 8; nt++) {
                int ncol = wn * 64 + nt * 8 + gid;
                b[nt][0] = __float_as_uint(Bs[(kc + tig) * BS_LD + ncol]);
                b[nt][1] = __float_as_uint(Bs[(kc + tig + 4) * BS_LD + ncol]);
            }
#pragma unroll
            for (int mt = 0; mt < 4; mt++)
#pragma unroll
                for (int nt = 0; nt < 8; nt++)
                    mma_tf32(d[mt][nt], a[mt], b[nt]);
        }
    }

#pragma unroll
    for (int mt = 0; mt < 4; mt++) {
        int r0 = bm + wm * 64 + mt * 16 + gid;
        int r1 = r0 + 8;
#pragma unroll
        for (int nt = 0; nt < 8; nt++) {
            int c = bn + wn * 64 + nt * 8 + 2 * tig;
            float bx0 = bias ? bias[c] : 0.f;
            float bx1 = bias ? bias[c + 1] : 0.f;
            if (r0 < M) {
                float2 v = make_float2(d[mt][nt][0] + bx0, d[mt][nt][1] + bx1);
                *(float2*)&C[(size_t)r0 * 512 + c] = v;
            }
            if (r1 < M) {
                float2 v = make_float2(d[mt][nt][2] + bx0, d[mt][nt][3] + bx1);
                *(float2*)&C[(size_t)r1 * 512 + c] = v;
            }
        }
    }
}

// ---------------- a_s / a_d -------------------------------------------------
__global__ void dots_kernel(const float* __restrict__ att_s,
                            const float* __restrict__ att_d, int Nn) {
    long long gt = (long long)blockIdx.x * blockDim.x + threadIdx.x;
    int n = (int)(gt >> 5), lane = (int)(gt & 31);
    if (n >= Nn) return;
    const float4* hr = (const float4*)(g_h + (size_t)n * 512);
    const float4* vs = (const float4*)att_s;
    const float4* vd = (const float4*)att_d;
    float s1 = 0.f, s2 = 0.f;
#pragma unroll
    for (int i = lane; i < 128; i += 32) {
        float4 h = hr[i], a = vs[i], b = vd[i];
        s1 += h.x * a.x + h.y * a.y + h.z * a.z + h.w * a.w;
        s2 += h.x * b.x + h.y * b.y + h.z * b.z + h.w * b.w;
    }
#pragma unroll
    for (int o = 16; o; o >>= 1) {
        s1 += __shfl_xor_sync(0xffffffffu, s1, o);
        s2 += __shfl_xor_sync(0xffffffffu, s2, o);
    }
    if (lane == 0) { g_as[n] = s1; g_ad[n] = s2; }
}

// ---------------- per-edge exp ----------------------------------------------
__global__ void edge_exp_kernel(int E, int Nn) {
    int i = blockIdx.x * blockDim.x + threadIdx.x;
    if (i >= E + Nn) return;
    int s, d;
    if (i < E) { s = g_src[i]; d = g_dst[i]; }
    else       { s = d = i - E; }
    float e = g_as[s] + g_ad[d];
    e = e > 0.0f ? e : 0.2f * e;
    g_ex[i] = expf(e);
}

// ---------------- CSR gather aggregation ------------------------------------
// hconv[n] = pre_rnd(b_conv + (sum_e ex_e * h[src_e]) / ssum)  (tf32-ready)
__global__ void aggregate_gather_kernel(const float* __restrict__ b_conv,
                                        int E, int Nn) {
    long long gt = (long long)blockIdx.x * blockDim.x + threadIdx.x;
    int n = (int)(gt >> 5), lane = (int)(gt & 31);
    if (n >= Nn) return;

    float4 acc[4];
    float w0 = g_ex[E + n];
    float ssum = w0;
    {
        const float4* hr = (const float4*)(g_h + (size_t)n * 512);
#pragma unroll
        for (int i = 0; i < 4; i++) {
            float4 v = hr[lane + i * 32];
            acc[i] = make_float4(w0 * v.x, w0 * v.y, w0 * v.z, w0 * v.w);
        }
    }
    int start = g_off[n], end = g_off[n + 1];
    for (int e = start; e < end; e++) {
        int s = g_cs[e];
        float w = g_ex[g_ce[e]];
        ssum += w;
        const float4* hr = (const float4*)(g_h + (size_t)s * 512);
#pragma unroll
        for (int i = 0; i < 4; i++) {
            float4 v = hr[lane + i * 32];
            acc[i].x += w * v.x; acc[i].y += w * v.y;
            acc[i].z += w * v.z; acc[i].w += w * v.w;
        }
    }
    float inv = 1.0f / (ssum + 1e-16f);
    float4* out = (float4*)(g_hconv + (size_t)n * 512);
    const float4* bc = (const float4*)b_conv;
#pragma unroll
    for (int i = 0; i < 4; i++) {
        int c = lane + i * 32;
        float4 b = bc[c];
        out[c] = make_float4(pre_rnd(b.x + acc[i].x * inv),
                             pre_rnd(b.y + acc[i].y * inv),
                             pre_rnd(b.z + acc[i].z * inv),
                             pre_rnd(b.w + acc[i].w * inv));
    }
}

// ---------------- attentional aggregation -----------------------------------
__global__ void gate_kernel(const float* __restrict__ Wg,
                            const float* __restrict__ bg, int Nn) {
    long long gt = (long long)blockIdx.x * blockDim.x + threadIdx.x;
    int n = (int)(gt >> 5), lane = (int)(gt & 31);
    if (n >= Nn) return;
    const float4* hr = (const float4*)(g_hconv + (size_t)n * 512);
    const float4* wg = (const float4*)Wg;
    float s = 0.f;
#pragma unroll
    for (int i = lane; i < 128; i += 32) {
        float4 h = hr[i], a = wg[i];
        s += h.x * a.x + h.y * a.y + h.z * a.z + h.w * a.w;
    }
#pragma unroll
    for (int o = 16; o; o >>= 1) s += __shfl_xor_sync(0xffffffffu, s, o);
    if (lane == 0) {
        float ex = expf(s + bg[0]);
        g_gex[n] = ex;
        atomicAdd(&g_gsum[g_b[n]], ex);
    }
}

__global__ void gate_norm_kernel(float* __restrict__ outg, int Nn) {
    int n = blockIdx.x * blockDim.x + threadIdx.x;
    if (n >= Nn) return;
    float gv = g_gex[n] / (g_gsum[g_b[n]] + 1e-16f);
    g_g[n] = gv;
    if (outg) outg[n] = gv;
}

__global__ __launch_bounds__(512)
void pool_kernel(int Nn) {
    int col = threadIdx.x;
    int n0 = blockIdx.x * 128;
    int nend = n0 + 128; if (nend > Nn) nend = Nn;
    double acc = 0.0; int cur = -1;
    for (int n = n0; n < nend; n++) {
        int b = g_b[n];
        if (b != cur) {
            if (cur >= 0) atomicAdd(&g_pooled[cur * DHC + col], acc);
            acc = 0.0; cur = b;
        }
        acc += (double)g_g[n] * (double)g_xn[(size_t)n * 512 + col];
    }
    if (cur >= 0) atomicAdd(&g_pooled[cur * DHC + col], acc);
}

// ---------------- classifier head -------------------------------------------
__global__ void z1_kernel(const float* __restrict__ W1, const float* __restrict__ b1) {
    int idx = blockIdx.x * blockDim.x + threadIdx.x;
    if (idx >= GMAX * DHC) return;
    int g = idx >> 9, t = idx & 511;
    const double* pr = g_pooled + g * DHC;
    double s = (double)b1[t];
    for (int k = 0; k < 512; k++) s += pr[k] * (double)W1[k * 512 + t];
    g_z1[idx] = (float)(s > 0.0 ? s : 0.0);
}

__global__ void z2_kernel(const float* __restrict__ W2, const float* __restrict__ b2,
                          float* __restrict__ out, int write_head) {
    int w = threadIdx.x >> 5, lane = threadIdx.x & 31;
    if (w >= GMAX) return;
    double s = 0.0;
    for (int t = lane; t < 512; t += 32) s += (double)g_z1[w * DHC + t] * (double)W2[t];
#pragma unroll
    for (int o = 16; o; o >>= 1) s += __shfl_xor_sync(0xffffffffu, s, o);
    if (lane == 0 && write_head) {
        double z = s + (double)b2[0];
        out[w] = (float)(1.0 / (1.0 + exp(-z)));
    }
}

// ---------------- launch -----------------------------------------------------
extern "C" void kernel_launch(void* const* d_in, const int* in_sizes, int n_in,
                              void* d_out, int out_size) {
    const float* x       = (const float*)d_in[0];
    const void*  ei      = d_in[1];
    const void*  batch   = d_in[2];
    const float* W       = (const float*)d_in[3];
    const float* att_src = (const float*)d_in[4];
    const float* att_dst = (const float*)d_in[5];
    const float* b_conv  = (const float*)d_in[6];
    const float* Wg      = (const float*)d_in[7];
    const float* bg      = (const float*)d_in[8];
    const float* Wn      = (const float*)d_in[9];
    const float* bn      = (const float*)d_in[10];
    const float* W1      = (const float*)d_in[11];
    const float* b1      = (const float*)d_in[12];
    const float* W2      = (const float*)d_in[13];
    const float* b2      = (const float*)d_in[14];

    const int Nn  = in_sizes[0] / 512;
    int wpi = in_sizes[2] / (Nn > 0 ? Nn : 1); if (wpi < 1) wpi = 1;
    const int E   = in_sizes[1] / (2 * wpi);
    const int tot = E + Nn;
    const int is64 = (wpi == 2) ? 1 : 0;

    float* dout = (float*)d_out;
    float* gdst = nullptr;
    if (out_size >= Nn) gdst = dout + (out_size - Nn);
    int write_head = (out_size != Nn) ? 1 : 0;

    cudaFuncSetAttribute(sgemm_tf32_kernel,
                         cudaFuncAttributeMaxDynamicSharedMemorySize, SMEM_BYTES);

    const int T = 256;
    setup_kernel<<<512, T>>>(dout, out_size, Nn);                           // 0
    decode_kernel<<<((E > Nn ? E : Nn) + T - 1) / T, T>>>(ei, batch, E, Nn,
                                                          is64, is64);      // 1
    pre_round_kernel<<<1024, T>>>(x, W, Wn, Nn);                            // 2
    {
        dim3 grid(512 / BN, (Nn + BM - 1) / BM);
        sgemm_tf32_kernel<<<grid, 128, SMEM_BYTES>>>(nullptr, Nn, 0);       // 3 (profiled)
    }
    hist_kernel<<<(E + T - 1) / T, T>>>(E);
    scan_kernel<<<1, 1024>>>(Nn);
    scatter_kernel<<<(E + T - 1) / T, T>>>(E);
    dots_kernel<<<((long long)Nn * 32 + T - 1) / T, T>>>(att_src, att_dst, Nn);
    edge_exp_kernel<<<(tot + T - 1) / T, T>>>(E, Nn);
    aggregate_gather_kernel<<<((long long)Nn * 32 + T - 1) / T, T>>>(b_conv, E, Nn);
    {
        dim3 grid(512 / BN, (Nn + BM - 1) / BM);
        sgemm_tf32_kernel<<<grid, 128, SMEM_BYTES>>>(bn, Nn, 1);
    }
    gate_kernel<<<((long long)Nn * 32 + T - 1) / T, T>>>(Wg, bg, Nn);
    gate_norm_kernel<<<(Nn + T - 1) / T, T>>>(gdst, Nn);
    pool_kernel<<<(Nn + 127) / 128, 512>>>(Nn);
    z1_kernel<<<(GMAX * DHC + T - 1) / T, T>>>(W1, b1);
    z2_kernel<<<1, 256>>>(W2, b2, dout, write_head);
}